// round 5
// baseline (speedup 1.0000x reference)
#include <cuda_runtime.h>

#define BIGZ 1000000.0f
constexpr int N_ = 8, H_ = 512, W_ = 512, C_ = 32, F_ = 20000, V_ = 10002;
constexpr int HW = H_ * W_;  // 262144

constexpr long long OFF_OUTMAP = 0LL;
constexpr long long OFF_VV     = 67108864LL;
constexpr long long OFF_MASK   = 67118866LL;
constexpr long long OFF_ZB     = 69216018LL;
constexpr long long OFF_P      = 71313170LL;
constexpr long long OFF_D      = 73410322LL;
constexpr long long OFF_BC     = 75507474LL;

// zero at module load; vertex_k restores all-zero after each use, so every
// graph replay sees the same initial state.
__device__ int g_face_flag[F_];

__device__ __forceinline__ void stcs4(float* p, float a, float b, float c, float d) {
    float4 v = make_float4(a, b, c, d);
    __stcs((float4*)p, v);
}
__device__ __forceinline__ void stcs2(float* p, float a, float b) {
    float2 v = make_float2(a, b);
    __stcs((float2*)p, v);
}

// ---------------------------------------------------------------------------
// Fused per-pixel pass, 4 pixels/thread. Key restructure vs R4: the color
// gather+einsum runs ONCE per pixel (for its unique valid layer) instead of
// being issued (predicated) for all 8 layers. Pixels with != 1 valid layer
// (probability ~2e-5) take a scalar fix-up path.
// ---------------------------------------------------------------------------
__global__ __launch_bounds__(128) void pixel_k(
    const float* __restrict__ zbuf,
    const int*   __restrict__ ptf,
    const float* __restrict__ bary,
    const float* __restrict__ dists,
    const float* __restrict__ fm,
    float*       __restrict__ out)
{
    int g = blockIdx.x * blockDim.x + threadIdx.x;  // 0 .. HW/4-1
    if (g < V_) out[OFF_VV + g] = 0.0f;
    int pix = g << 2;

    // ---- pass 1: coverage count + first-argmin over the 8 layers ----------
    float z[8][4];
    float minv[4];
    int   mini[4];
    int   cnt[4];
#pragma unroll
    for (int j = 0; j < 4; j++) { minv[j] = 3.0e38f; mini[j] = 0; cnt[j] = 0; }

#pragma unroll
    for (int n = 0; n < 8; n++) {
        float4 zz = __ldcs((const float4*)(zbuf + n * HW + pix));
        z[n][0] = zz.x; z[n][1] = zz.y; z[n][2] = zz.z; z[n][3] = zz.w;
#pragma unroll
        for (int j = 0; j < 4; j++) {
            float v = z[n][j];
            cnt[j] += (v > -1.0f) ? 1 : 0;
            float tmp = (v < 0.0f) ? BIGZ : v;
            if (tmp < minv[j]) { minv[j] = tmp; mini[j] = n; }
        }
    }

    // ---- pass 2: small outputs + record the (usually unique) valid layer --
    int   vlayer[4] = {-1, -1, -1, -1};
    int   vcount[4] = {0, 0, 0, 0};
    int   prs[4]    = {0, 0, 0, 0};
    float s0[4] = {0, 0, 0, 0}, s1[4] = {0, 0, 0, 0}, s2[4] = {0, 0, 0, 0};

#pragma unroll
    for (int n = 0; n < 8; n++) {
        int4   pf4 = __ldcs((const int4*)(ptf + n * HW + pix));
        float4 d4  = __ldcs((const float4*)(dists + n * HW + pix));
        const float* bptr = bary + (long long)(n * HW + pix) * 3;
        float4 bA = __ldcs((const float4*)(bptr));
        float4 bB = __ldcs((const float4*)(bptr + 4));
        float4 bC = __ldcs((const float4*)(bptr + 8));
        float bin[12] = {bA.x, bA.y, bA.z, bA.w, bB.x, bB.y, bB.z, bB.w,
                         bC.x, bC.y, bC.z, bC.w};
        int   pf[4] = {pf4.x, pf4.y, pf4.z, pf4.w};
        float dd[4] = {d4.x, d4.y, d4.z, d4.w};

        float zbo[4], po[4], dto[4], mo[4], bco[12];
#pragma unroll
        for (int j = 0; j < 4; j++) {
            bool dup = (cnt[j] > 1) && (mini[j] != n);
            int  p   = dup ? -1 : pf[j];
            zbo[j]   = dup ? -1.0f : z[n][j];
            po[j]    = (float)p;
            dto[j]   = dup ? -1.0f : dd[j];
            float b0 = dup ? -1.0f : bin[3 * j + 0];
            float b1 = dup ? -1.0f : bin[3 * j + 1];
            float b2 = dup ? -1.0f : bin[3 * j + 2];
            bco[3 * j + 0] = b0;
            bco[3 * j + 1] = b1;
            bco[3 * j + 2] = b2;
            mo[j] = (z[n][j] >= 0.0f) ? 1.0f : 0.0f;
            if (p >= 0) {
                g_face_flag[p] = 1;       // idempotent flag store
                vcount[j]++;
                vlayer[j] = n;
                prs[j]    = p;
                s0[j] = b0; s1[j] = b1; s2[j] = b2;
            }
        }

        long long base = (long long)n * HW + pix;
        float* zp = out + OFF_ZB + base;
        stcs2(zp,     zbo[0], zbo[1]); stcs2(zp + 2, zbo[2], zbo[3]);
        float* pp = out + OFF_P + base;
        stcs2(pp,     po[0], po[1]);   stcs2(pp + 2, po[2], po[3]);
        float* dp = out + OFF_D + base;
        stcs2(dp,     dto[0], dto[1]); stcs2(dp + 2, dto[2], dto[3]);
        float* mp = out + OFF_MASK + base;
        stcs2(mp,     mo[0], mo[1]);   stcs2(mp + 2, mo[2], mo[3]);
        float* bp = out + OFF_BC + base * 3;
#pragma unroll
        for (int k = 0; k < 6; k++)
            stcs2(bp + 2 * k, bco[2 * k], bco[2 * k + 1]);
    }

    // fast path only valid when exactly one layer survives
#pragma unroll
    for (int j = 0; j < 4; j++)
        if (vcount[j] != 1) vlayer[j] = -1;

    // ---- color pass: one gather per pixel, zero-fill other layers ----------
    float* om = out + OFF_OUTMAP + pix;
#pragma unroll
    for (int cq = 0; cq < 8; cq++) {
        int c = cq * 4;
        float a[4][4];
#pragma unroll
        for (int j = 0; j < 4; j++) {
            if (vlayer[j] >= 0) {
                const float* fb = fm + prs[j] * 96 + c;
                float4 f0 = *(const float4*)(fb);
                float4 f1 = *(const float4*)(fb + 32);
                float4 f2 = *(const float4*)(fb + 64);
                a[j][0] = s0[j] * f0.x + s1[j] * f1.x + s2[j] * f2.x;
                a[j][1] = s0[j] * f0.y + s1[j] * f1.y + s2[j] * f2.y;
                a[j][2] = s0[j] * f0.z + s1[j] * f1.z + s2[j] * f2.z;
                a[j][3] = s0[j] * f0.w + s1[j] * f1.w + s2[j] * f2.w;
            } else {
                a[j][0] = a[j][1] = a[j][2] = a[j][3] = 0.0f;
            }
        }
#pragma unroll
        for (int n = 0; n < 8; n++) {
            bool m0 = (vlayer[0] == n), m1 = (vlayer[1] == n);
            bool m2 = (vlayer[2] == n), m3 = (vlayer[3] == n);
            float* omn = om + (long long)n * C_ * HW;
#pragma unroll
            for (int k = 0; k < 4; k++)
                stcs4(omn + (long long)(c + k) * HW,
                      m0 ? a[0][k] : 0.0f, m1 ? a[1][k] : 0.0f,
                      m2 ? a[2][k] : 0.0f, m3 ? a[3][k] : 0.0f);
        }
    }

    // ---- rare fix-up: pixels with 0 or >1 valid layers ---------------------
#pragma unroll
    for (int j = 0; j < 4; j++) {
        if (vcount[j] > 1 || (vcount[j] == 1 && vlayer[j] == -1)) {}  // normalize
        if (vcount[j] != 1 && vcount[j] > 0) {
            for (int n = 0; n < 8; n++) {
                int p = ptf[n * HW + pix + j];
                bool dup = (cnt[j] > 1) && (mini[j] != n);
                p = dup ? -1 : p;
                if (p >= 0) {
                    const float* bq = bary + ((long long)(n * HW + pix + j)) * 3;
                    float b0 = bq[0], b1 = bq[1], b2 = bq[2];
                    const float* fb = fm + p * 96;
                    float* dst = out + OFF_OUTMAP + (long long)n * C_ * HW + pix + j;
                    for (int c = 0; c < 32; c++)
                        dst[(long long)c * HW] =
                            b0 * fb[c] + b1 * fb[32 + c] + b2 * fb[64 + c];
                }
            }
        }
    }
}

// ---------------------------------------------------------------------------
// Face visibility -> vertex visibility scatter; clears flags for next replay.
// ---------------------------------------------------------------------------
__global__ __launch_bounds__(128) void vertex_k(const int* __restrict__ faces,
                                                float* __restrict__ out) {
    int f = blockIdx.x * blockDim.x + threadIdx.x;
    if (f < F_) {
        int flag = g_face_flag[f];
        int v0 = __ldg(faces + 3 * f + 0);
        int v1 = __ldg(faces + 3 * f + 1);
        int v2 = __ldg(faces + 3 * f + 2);
        if (flag) {
            out[OFF_VV + v0] = 1.0f;
            out[OFF_VV + v1] = 1.0f;
            out[OFF_VV + v2] = 1.0f;
            g_face_flag[f] = 0;
        }
    }
}

extern "C" void kernel_launch(void* const* d_in, const int* in_sizes, int n_in,
                              void* d_out, int out_size) {
    const float* zbuf  = (const float*)d_in[0];
    const int*   ptf   = (const int*)d_in[1];
    const float* bary  = (const float*)d_in[2];
    const float* dists = (const float*)d_in[3];
    const float* fm    = (const float*)d_in[4];
    const int*   faces = (const int*)d_in[5];
    float* out = (float*)d_out;

    pixel_k<<<(HW / 4) / 128, 128>>>(zbuf, ptf, bary, dists, fm, out);
    vertex_k<<<(F_ + 127) / 128, 128>>>(faces, out);
}